// round 10
// baseline (speedup 1.0000x reference)
#include <cuda_runtime.h>
#include <cstdint>

#define Nn 8192
#define Dd 1024

// Persistent scratch. g_pre[j] = PRE-activation of skips[j], j=0..7.
__device__ float g_pre[8][32][Dd];

#define AP 66   // As pitch in floats per d-row (64 data + 2 pad)
#define BP 66   // Bs pitch in floats per b-row

// One shared workspace per block, declared ONCE per kernel (R6 lesson).
struct SmemT {
    float         As[128 * AP];     // [d][k*2 + v] tf32 hi/lo interleaved (33792 B)
    float         Bs[32 * BP];      // [b][k*2 + v]                        ( 8448 B)
    unsigned char adjs[32 * 132];   // [k][d] bytes                        ( 4224 B)
};                                  // total 46464 B

__device__ __forceinline__ float tf32r(float x) {
    uint32_t r;
    asm("cvt.rna.tf32.f32 %0, %1;" : "=r"(r) : "f"(x));
    return __uint_as_float(r);
}
__device__ __forceinline__ float sig(float v) {
    return 1.f / (1.f + __expf(-v));
}
__device__ __forceinline__ void redadd(float* p, float v) {
    asm volatile("red.global.add.f32 [%0], %1;" :: "l"(p), "f"(v) : "memory");
}
// D += A(tf32) * B(tf32), m16n8k8, fp32 accumulate
__device__ __forceinline__ void mma8(float& c0, float& c1, float& c2, float& c3,
                                     uint32_t a0, uint32_t a1, uint32_t a2, uint32_t a3,
                                     uint32_t b0, uint32_t b1) {
    asm volatile("mma.sync.aligned.m16n8k8.row.col.f32.tf32.tf32.f32 "
                 "{%0,%1,%2,%3}, {%4,%5,%6,%7}, {%8,%9}, {%0,%1,%2,%3};"
                 : "+f"(c0), "+f"(c1), "+f"(c2), "+f"(c3)
                 : "r"(a0), "r"(a1), "r"(a2), "r"(a3), "r"(b0), "r"(b1));
}

// ---------------------------------------------------------------------------
// Masked matvec via mma.sync tf32 hi/lo split:
//   out[b, d0+d] += sum_n act(X[b,n]) * W[d0+d,n] * (adjA[n*Nn + d0+d] != 0)
// Block: 256 threads (8 warps). Tile M=128 (d) x N=32 (b); warp owns 16 d.
// K processed in nchunks chunks of 32. Accumulators live in registers.
// ---------------------------------------------------------------------------
template <bool SIG>
__device__ __forceinline__ void mv_mma(
    SmemT* sm,
    const float* __restrict__ W, int wstride,
    const int* __restrict__ adjA,
    const float* __restrict__ X, int xstride,
    float* __restrict__ out,
    int d0, int n0, int nchunks)
{
    const int tid  = threadIdx.x;
    const int wid  = tid >> 5, lane = tid & 31;
    const int g    = lane >> 2;          // group id (0..7)
    const int tg   = lane & 3;           // thread-in-group (0..3)
    const int mw   = wid * 16;           // warp's d base within 128
    const int kq   = tid & 7;            // staging: 4-float k group
    const int dw   = tid >> 3;           // staging: 0..31
    const int dq   = tid & 31;           // adj staging: 4-int d group
    const int nr   = tid >> 5;           // adj staging: k-row group

    float c[4][4];                       // [ntile][c0..c3]
#pragma unroll
    for (int i = 0; i < 4; i++)
#pragma unroll
        for (int q = 0; q < 4; q++) c[i][q] = 0.f;

    for (int ch = 0; ch < nchunks; ch++) {
        const int nb = n0 + ch * 32;
        if (ch) __syncthreads();         // prev MMA phase done reading smem

        // --- LDGs up front (high MLP) ---
        float4 wreg[4];
#pragma unroll
        for (int p = 0; p < 4; p++) {
            int d = p * 32 + dw;
            wreg[p] = *(const float4*)&W[(size_t)(d0 + d) * wstride + nb + kq * 4];
        }
        int4 areg[4];
#pragma unroll
        for (int q = 0; q < 4; q++) {
            int k = q * 8 + nr;
            areg[q] = *(const int4*)&adjA[(size_t)(nb + k) * Nn + d0 + dq * 4];
        }
        float4 xv = *(const float4*)&X[(size_t)dw * xstride + nb + kq * 4];

        // --- stage adj bytes [k][d] + B (activations split) ---
#pragma unroll
        for (int q = 0; q < 4; q++) {
            int k = q * 8 + nr;
            *(uchar4*)&sm->adjs[k * 132 + dq * 4] =
                make_uchar4((unsigned char)(areg[q].x != 0),
                            (unsigned char)(areg[q].y != 0),
                            (unsigned char)(areg[q].z != 0),
                            (unsigned char)(areg[q].w != 0));
        }
        {
            if (SIG) {
                xv.x = sig(xv.x); xv.y = sig(xv.y);
                xv.z = sig(xv.z); xv.w = sig(xv.w);
            }
            float* bp = &sm->Bs[dw * BP + kq * 8];
            float h0 = tf32r(xv.x), h1 = tf32r(xv.y);
            float h2 = tf32r(xv.z), h3 = tf32r(xv.w);
            *(float2*)(bp + 0) = make_float2(h0, tf32r(xv.x - h0));
            *(float2*)(bp + 2) = make_float2(h1, tf32r(xv.y - h1));
            *(float2*)(bp + 4) = make_float2(h2, tf32r(xv.z - h2));
            *(float2*)(bp + 6) = make_float2(h3, tf32r(xv.w - h3));
        }
        __syncthreads();                 // adj bytes visible

        // --- stage A: mask W, split, interleaved store ---
        const unsigned char* ab = sm->adjs;
#pragma unroll
        for (int p = 0; p < 4; p++) {
            int d = p * 32 + dw;
            float4 w = wreg[p];
            if (!ab[(kq * 4 + 0) * 132 + d]) w.x = 0.f;
            if (!ab[(kq * 4 + 1) * 132 + d]) w.y = 0.f;
            if (!ab[(kq * 4 + 2) * 132 + d]) w.z = 0.f;
            if (!ab[(kq * 4 + 3) * 132 + d]) w.w = 0.f;
            float* ap = &sm->As[d * AP + kq * 8];
            float h0 = tf32r(w.x), h1 = tf32r(w.y);
            float h2 = tf32r(w.z), h3 = tf32r(w.w);
            *(float2*)(ap + 0) = make_float2(h0, tf32r(w.x - h0));
            *(float2*)(ap + 2) = make_float2(h1, tf32r(w.y - h1));
            *(float2*)(ap + 4) = make_float2(h2, tf32r(w.z - h2));
            *(float2*)(ap + 6) = make_float2(h3, tf32r(w.w - h3));
        }
        __syncthreads();

        // --- MMA phase: 4 k-steps x 4 n-tiles x (hh + hl + lh) ---
#pragma unroll
        for (int ks = 0; ks < 4; ks++) {
            // A fragment (hi+lo pairs): slots (g,t), (g+8,t), (g,t+4), (g+8,t+4)
            float2 a0 = *(const float2*)&sm->As[(mw + g)     * AP + (ks * 8 + tg)     * 2];
            float2 a1 = *(const float2*)&sm->As[(mw + g + 8) * AP + (ks * 8 + tg)     * 2];
            float2 a2 = *(const float2*)&sm->As[(mw + g)     * AP + (ks * 8 + tg + 4) * 2];
            float2 a3 = *(const float2*)&sm->As[(mw + g + 8) * AP + (ks * 8 + tg + 4) * 2];
            uint32_t ah0 = __float_as_uint(a0.x), al0 = __float_as_uint(a0.y);
            uint32_t ah1 = __float_as_uint(a1.x), al1 = __float_as_uint(a1.y);
            uint32_t ah2 = __float_as_uint(a2.x), al2 = __float_as_uint(a2.y);
            uint32_t ah3 = __float_as_uint(a3.x), al3 = __float_as_uint(a3.y);
#pragma unroll
            for (int nt = 0; nt < 4; nt++) {
                // B fragment: (t, g), (t+4, g) with col = b = nt*8 + g
                float2 b0 = *(const float2*)&sm->Bs[(nt * 8 + g) * BP + (ks * 8 + tg)     * 2];
                float2 b1 = *(const float2*)&sm->Bs[(nt * 8 + g) * BP + (ks * 8 + tg + 4) * 2];
                uint32_t bh0 = __float_as_uint(b0.x), bl0 = __float_as_uint(b0.y);
                uint32_t bh1 = __float_as_uint(b1.x), bl1 = __float_as_uint(b1.y);
                mma8(c[nt][0], c[nt][1], c[nt][2], c[nt][3],
                     ah0, ah1, ah2, ah3, bh0, bh1);
                mma8(c[nt][0], c[nt][1], c[nt][2], c[nt][3],
                     ah0, ah1, ah2, ah3, bl0, bl1);
                mma8(c[nt][0], c[nt][1], c[nt][2], c[nt][3],
                     al0, al1, al2, al3, bh0, bh1);
            }
        }
    }

    // epilogue: C fragment (m16n8): c0:(g,2t) c1:(g,2t+1) c2:(g+8,2t) c3:(g+8,2t+1)
    const int drow = d0 + mw + g;
#pragma unroll
    for (int nt = 0; nt < 4; nt++) {
        int b = nt * 8 + 2 * tg;
        redadd(&out[(size_t)b       * Dd + drow],     c[nt][0]);
        redadd(&out[(size_t)(b + 1) * Dd + drow],     c[nt][1]);
        redadd(&out[(size_t)b       * Dd + drow + 8], c[nt][2]);
        redadd(&out[(size_t)(b + 1) * Dd + drow + 8], c[nt][3]);
    }
}

// ---------------------------------------------------------------------------

// g_pre[0][b][d] = b_in[d]; g_pre[i][b][d] = b_h[i-1][d] for i=1..7
__global__ void init_kernel(const float* __restrict__ b_in,
                            const float* __restrict__ b_h) {
    int idx = blockIdx.x * 256 + threadIdx.x;   // 1024 blocks
    int d = idx & 1023, i = idx >> 15;
    ((float*)g_pre)[idx] = (i == 0) ? b_in[d] : b_h[(i - 1) * Dd + d];
}

// g_pre[0] += h @ Wr_m(0).T  (n in [1024, 8192)). grid (8, 56), nchunks=4.
__global__ void __launch_bounds__(256, 3) r0_kernel(
    const float* __restrict__ W_r, const int* __restrict__ adj,
    const float* __restrict__ h)
{
    __shared__ SmemT sm;
    mv_mma<false>(&sm, W_r, Nn, adj, h, Nn, &g_pre[0][0][0],
                  blockIdx.x * 128, 1024 + blockIdx.y * 128, 4);
}

// g_pre[0] += x @ W_in.T
__global__ void prelayer_kernel(
    const float* __restrict__ x, const float* __restrict__ W_in)
{
    int idx = blockIdx.x * 256 + threadIdx.x;  // 32768
    int d = idx & 1023, bt = idx >> 10;
    const float4* xr = (const float4*)(x + bt * 256);
    const float4* wr = (const float4*)(W_in + (size_t)d * 256);
    float s = 0.f;
#pragma unroll 8
    for (int c = 0; c < 64; c++) {
        float4 aa = xr[c], bb = wr[c];
        s += aa.x * bb.x + aa.y * bb.y + aa.z * bb.z + aa.w * bb.w;
    }
    g_pre[0][bt][d] += s;
}

// Fused launch after g_pre[j] complete. grid (8, (13-2j)*ksl):
//   g == 0         : pre[j+1] += sig(pre[j]) @ Wh_m(j).T
//   g in [1, 7-j)  : pre[i+1] += sig(pre[j]) @ Ws-block(i, j).T  (i = j+g)
//   else           : pre[j+1] += h @ Wr_m(j+1).T slice
__global__ void __launch_bounds__(256, 3) L_kernel(
    const float* __restrict__ W_h, const float* __restrict__ W_s,
    const float* __restrict__ W_r, const int* __restrict__ adj,
    const float* __restrict__ h, int j, int nch, int ksl)
{
    __shared__ SmemT sm;
    int d0 = blockIdx.x * 128;
    int g = blockIdx.y / ksl;
    int nloc = (blockIdx.y % ksl) * 32 * nch;
    if (g == 0) {
        mv_mma<true>(&sm, W_h + (size_t)j * Dd * Dd, Dd,
                     adj + (size_t)j * Dd * Nn + (j + 1) * Dd,
                     &g_pre[j][0][0], Dd,
                     &g_pre[j + 1][0][0], d0, nloc, nch);
    } else if (g <= 6 - j) {
        int i = j + g;
        // X rebased so X[b*Dd + n] == g_pre[j][b][n - j*1024]
        mv_mma<true>(&sm, W_s + (size_t)(i - 1) * Dd * 6144, 6144,
                     adj + (i + 1) * Dd,
                     &g_pre[j][0][0] - j * 1024, Dd,
                     &g_pre[i + 1][0][0], d0, j * 1024 + nloc, nch);
    } else {
        int u = g - (7 - j);
        int k = j + 1;
        mv_mma<false>(&sm, W_r + (size_t)k * Dd * Nn, Nn,
                      adj + k * Dd,
                      h, Nn,
                      &g_pre[j + 1][0][0], d0, (k + 1 + u) * 1024 + nloc, nch);
    }
}

// out = sig(g_pre[7]) @ W_o.T + b_o
__global__ void final_kernel(const float* __restrict__ W_o,
                             const float* __restrict__ b_o,
                             float* __restrict__ out)
{
    int idx = blockIdx.x * 256 + threadIdx.x;  // 2048
    int o = idx & 63, bt = idx >> 6;
    const float4* sr = (const float4*)&g_pre[7][bt][0];
    const float4* wr = (const float4*)(W_o + (size_t)o * Dd);
    float s = 0.f;
#pragma unroll 8
    for (int c = 0; c < 256; c++) {
        float4 aa = sr[c], bb = wr[c];
        s += sig(aa.x) * bb.x + sig(aa.y) * bb.y + sig(aa.z) * bb.z + sig(aa.w) * bb.w;
    }
    out[bt * 64 + o] = s + b_o[o];
}

// ---------------------------------------------------------------------------

extern "C" void kernel_launch(void* const* d_in, const int* in_sizes, int n_in,
                              void* d_out, int out_size)
{
    const float* x    = (const float*)d_in[0];
    const float* h    = (const float*)d_in[1];
    const int*   adj  = (const int*)d_in[2];
    const float* W_in = (const float*)d_in[3];
    const float* b_in = (const float*)d_in[4];
    const float* W_h  = (const float*)d_in[5];
    const float* b_h  = (const float*)d_in[6];
    const float* W_r  = (const float*)d_in[7];
    const float* W_s  = (const float*)d_in[8];
    const float* W_o  = (const float*)d_in[9];
    const float* b_o  = (const float*)d_in[10];
    float* out = (float*)d_out;

    init_kernel<<<1024, 256>>>(b_in, b_h);
    r0_kernel<<<dim3(8, 56), 256>>>(W_r, adj, h);
    prelayer_kernel<<<128, 256>>>(x, W_in);

    for (int j = 0; j < 7; j++) {
        int nch = (j <= 3) ? 4 : ((j <= 5) ? 2 : 1);
        int ksl = 1024 / (32 * nch);
        L_kernel<<<dim3(8, (13 - 2 * j) * ksl), 256>>>(
            W_h, W_s, W_r, adj, h, j, nch, ksl);
    }

    final_kernel<<<8, 256>>>(W_o, b_o, out);
}

// round 11
// speedup vs baseline: 1.3193x; 1.3193x over previous
#include <cuda_runtime.h>
#include <cstdint>

#define Nn 8192
#define Dd 1024

// Persistent scratch. g_pre[j] = PRE-activation of skips[j], j=0..7.
__device__ float g_pre[8][32][Dd];

#define APW 20   // uint32 words per bf16 tile row (16 data + 4 pad, conflict-free frags)

// One shared workspace per block, declared ONCE per kernel (R6 lesson). ~26.2 KB.
struct SmemB {
    uint32_t Ah[128 * APW];   // masked W hi-plane, bf16x2 per word   (10240 B)
    uint32_t Al[128 * APW];   // lo-plane                              (10240 B)
    uint32_t Bh[32 * APW];    // activations hi-plane                  ( 2560 B)
    uint32_t Bl[32 * APW];    //                                        ( 2560 B)
    uint32_t kbit[32 * 5];    // ballot masks: kbit[k*5 + j] bits over d (640 B)
};

__device__ __forceinline__ float sig(float v) {
    return 1.f / (1.f + __expf(-v));
}
__device__ __forceinline__ void redadd(float* p, float v) {
    asm volatile("red.global.add.f32 [%0], %1;" :: "l"(p), "f"(v) : "memory");
}
// pack two floats to bf16x2 (e0 -> low half, e1 -> high half)
__device__ __forceinline__ uint32_t pk2(float e1, float e0) {
    uint32_t r;
    asm("cvt.rn.bf16x2.f32 %0, %1, %2;" : "=r"(r) : "f"(e1), "f"(e0));
    return r;
}
__device__ __forceinline__ float lo_f(uint32_t r) { return __uint_as_float(r << 16); }
__device__ __forceinline__ float hi_f(uint32_t r) { return __uint_as_float(r & 0xFFFF0000u); }

// split 4 floats into bf16 hi/lo planes and store (one STS.64 per plane)
__device__ __forceinline__ void split_store(uint32_t* Hp, uint32_t* Lp, float4 v) {
    uint32_t h01 = pk2(v.y, v.x);
    uint32_t h23 = pk2(v.w, v.z);
    float l0 = v.x - lo_f(h01), l1 = v.y - hi_f(h01);
    float l2 = v.z - lo_f(h23), l3 = v.w - hi_f(h23);
    *(uint2*)Hp = make_uint2(h01, h23);
    *(uint2*)Lp = make_uint2(pk2(l1, l0), pk2(l3, l2));
}

// D += A(bf16) * B(bf16), m16n8k16, fp32 accumulate
__device__ __forceinline__ void mma16(float* c,
                                      uint32_t a0, uint32_t a1, uint32_t a2, uint32_t a3,
                                      uint32_t b0, uint32_t b1) {
    asm volatile("mma.sync.aligned.m16n8k16.row.col.f32.bf16.bf16.f32 "
                 "{%0,%1,%2,%3}, {%4,%5,%6,%7}, {%8,%9}, {%0,%1,%2,%3};"
                 : "+f"(c[0]), "+f"(c[1]), "+f"(c[2]), "+f"(c[3])
                 : "r"(a0), "r"(a1), "r"(a2), "r"(a3), "r"(b0), "r"(b1));
}

// ---------------------------------------------------------------------------
// Masked matvec via mma.sync bf16 hi/lo split (3 products, error ~2^-18):
//   out[b, d0+d] += sum_n act(X[b,n]) * W[d0+d,n] * (adjA[n*Nn + d0+d] != 0)
// Block: 256 threads (8 warps). Tile M=128 (d) x N=32 (b); warp owns 16 d.
// K in nchunks chunks of 32. adj mask via warp ballots (1 bit/element).
// ---------------------------------------------------------------------------
template <bool SIG>
__device__ __forceinline__ void mv_mma(
    SmemB* sm,
    const float* __restrict__ W, int wstride,
    const int* __restrict__ adjA,
    const float* __restrict__ X, int xstride,
    float* __restrict__ out,
    int d0, int n0, int nchunks)
{
    const int tid  = threadIdx.x;
    const int wid  = tid >> 5, lane = tid & 31;
    const int g    = lane >> 2, tg = lane & 3;
    const int mw   = wid * 16;
    const int kq   = tid & 7;            // staging: 4-float k group
    const int dw   = tid >> 3;           // staging: 0..31
    const int jc   = dw & 3;             // ballot word select
    const int bsh  = dw >> 2;            // ballot bit base

    float c[4][4];
#pragma unroll
    for (int i = 0; i < 4; i++)
#pragma unroll
        for (int q = 0; q < 4; q++) c[i][q] = 0.f;

    for (int ch = 0; ch < nchunks; ch++) {
        const int nb = n0 + ch * 32;
        if (ch) __syncthreads();         // prev MMA phase done reading smem

        // --- LDGs up front (high MLP) ---
        float4 wreg[4];
#pragma unroll
        for (int p = 0; p < 4; p++) {
            int d = p * 32 + dw;
            wreg[p] = *(const float4*)&W[(size_t)(d0 + d) * wstride + nb + kq * 4];
        }
        float4 xv = *(const float4*)&X[(size_t)dw * xstride + nb + kq * 4];

        // --- adj -> per-k 128-bit masks via ballots (warp wid owns k = q*8+wid) ---
#pragma unroll
        for (int q = 0; q < 4; q++) {
            int k = q * 8 + wid;
            int4 av = *(const int4*)&adjA[(size_t)(nb + k) * Nn + d0 + lane * 4];
            uint32_t b0 = __ballot_sync(0xFFFFFFFFu, av.x != 0);
            uint32_t b1 = __ballot_sync(0xFFFFFFFFu, av.y != 0);
            uint32_t b2 = __ballot_sync(0xFFFFFFFFu, av.z != 0);
            uint32_t b3 = __ballot_sync(0xFFFFFFFFu, av.w != 0);
            if (lane < 4) {
                uint32_t v = (lane == 0) ? b0 : (lane == 1) ? b1
                           : (lane == 2) ? b2 : b3;
                sm->kbit[k * 5 + lane] = v;
            }
        }

        // --- B staging: activations, split, store ---
        {
            if (SIG) {
                xv.x = sig(xv.x); xv.y = sig(xv.y);
                xv.z = sig(xv.z); xv.w = sig(xv.w);
            }
            split_store(&sm->Bh[dw * APW + kq * 2], &sm->Bl[dw * APW + kq * 2], xv);
        }
        __syncthreads();                 // kbit + B visible

        // --- A staging: mask from ballots, split, store ---
        uint32_t m0 = sm->kbit[(kq * 4 + 0) * 5 + jc];
        uint32_t m1 = sm->kbit[(kq * 4 + 1) * 5 + jc];
        uint32_t m2 = sm->kbit[(kq * 4 + 2) * 5 + jc];
        uint32_t m3 = sm->kbit[(kq * 4 + 3) * 5 + jc];
#pragma unroll
        for (int p = 0; p < 4; p++) {
            int d = p * 32 + dw;
            int bp = p * 8 + bsh;        // = d >> 2
            float4 w = wreg[p];
            if (!((m0 >> bp) & 1u)) w.x = 0.f;
            if (!((m1 >> bp) & 1u)) w.y = 0.f;
            if (!((m2 >> bp) & 1u)) w.z = 0.f;
            if (!((m3 >> bp) & 1u)) w.w = 0.f;
            split_store(&sm->Ah[d * APW + kq * 2], &sm->Al[d * APW + kq * 2], w);
        }
        __syncthreads();

        // --- MMA phase: 2 k16-steps x 4 n-tiles x (hh + hl + lh) ---
#pragma unroll
        for (int ks = 0; ks < 2; ks++) {
            int u  = ks * 8 + tg;
            int r0 = (mw + g) * APW, r1 = (mw + g + 8) * APW;
            uint32_t ah0 = sm->Ah[r0 + u],     ah1 = sm->Ah[r1 + u];
            uint32_t ah2 = sm->Ah[r0 + u + 4], ah3 = sm->Ah[r1 + u + 4];
            uint32_t al0 = sm->Al[r0 + u],     al1 = sm->Al[r1 + u];
            uint32_t al2 = sm->Al[r0 + u + 4], al3 = sm->Al[r1 + u + 4];
#pragma unroll
            for (int nt = 0; nt < 4; nt++) {
                int bb = (nt * 8 + g) * APW + u;
                uint32_t bh0 = sm->Bh[bb], bh1 = sm->Bh[bb + 4];
                uint32_t bl0 = sm->Bl[bb], bl1 = sm->Bl[bb + 4];
                mma16(c[nt], ah0, ah1, ah2, ah3, bh0, bh1);
                mma16(c[nt], ah0, ah1, ah2, ah3, bl0, bl1);
                mma16(c[nt], al0, al1, al2, al3, bh0, bh1);
            }
        }
    }

    // epilogue: C m16n8: c0:(g,2tg) c1:(g,2tg+1) c2:(g+8,2tg) c3:(g+8,2tg+1)
    const int drow = d0 + mw + g;
#pragma unroll
    for (int nt = 0; nt < 4; nt++) {
        int b = nt * 8 + 2 * tg;
        redadd(&out[(size_t)b       * Dd + drow],     c[nt][0]);
        redadd(&out[(size_t)(b + 1) * Dd + drow],     c[nt][1]);
        redadd(&out[(size_t)b       * Dd + drow + 8], c[nt][2]);
        redadd(&out[(size_t)(b + 1) * Dd + drow + 8], c[nt][3]);
    }
}

// ---------------------------------------------------------------------------

// g_pre[0][b][d] = b_in[d]; g_pre[i][b][d] = b_h[i-1][d] for i=1..7
__global__ void init_kernel(const float* __restrict__ b_in,
                            const float* __restrict__ b_h) {
    int idx = blockIdx.x * 256 + threadIdx.x;   // 1024 blocks
    int d = idx & 1023, i = idx >> 15;
    ((float*)g_pre)[idx] = (i == 0) ? b_in[d] : b_h[(i - 1) * Dd + d];
}

// g_pre[0] += h @ Wr_m(0).T  (n in [1024, 8192)). grid (8, 56), nchunks=4.
__global__ void __launch_bounds__(256, 3) r0_kernel(
    const float* __restrict__ W_r, const int* __restrict__ adj,
    const float* __restrict__ h)
{
    __shared__ SmemB sm;
    mv_mma<false>(&sm, W_r, Nn, adj, h, Nn, &g_pre[0][0][0],
                  blockIdx.x * 128, 1024 + blockIdx.y * 128, 4);
}

// g_pre[0] += x @ W_in.T
__global__ void prelayer_kernel(
    const float* __restrict__ x, const float* __restrict__ W_in)
{
    int idx = blockIdx.x * 256 + threadIdx.x;  // 32768
    int d = idx & 1023, bt = idx >> 10;
    const float4* xr = (const float4*)(x + bt * 256);
    const float4* wr = (const float4*)(W_in + (size_t)d * 256);
    float s = 0.f;
#pragma unroll 8
    for (int c = 0; c < 64; c++) {
        float4 aa = xr[c], bb = wr[c];
        s += aa.x * bb.x + aa.y * bb.y + aa.z * bb.z + aa.w * bb.w;
    }
    g_pre[0][bt][d] += s;
}

// Fused launch after g_pre[j] complete. grid (8, (13-2j)*ksl):
//   g == 0         : pre[j+1] += sig(pre[j]) @ Wh_m(j).T
//   g in [1, 7-j)  : pre[i+1] += sig(pre[j]) @ Ws-block(i, j).T  (i = j+g)
//   else           : pre[j+1] += h @ Wr_m(j+1).T slice
__global__ void __launch_bounds__(256, 3) L_kernel(
    const float* __restrict__ W_h, const float* __restrict__ W_s,
    const float* __restrict__ W_r, const int* __restrict__ adj,
    const float* __restrict__ h, int j, int nch, int ksl)
{
    __shared__ SmemB sm;
    int d0 = blockIdx.x * 128;
    int g = blockIdx.y / ksl;
    int nloc = (blockIdx.y % ksl) * 32 * nch;
    if (g == 0) {
        mv_mma<true>(&sm, W_h + (size_t)j * Dd * Dd, Dd,
                     adj + (size_t)j * Dd * Nn + (j + 1) * Dd,
                     &g_pre[j][0][0], Dd,
                     &g_pre[j + 1][0][0], d0, nloc, nch);
    } else if (g <= 6 - j) {
        int i = j + g;
        // X rebased so X[b*Dd + n] == g_pre[j][b][n - j*1024]
        mv_mma<true>(&sm, W_s + (size_t)(i - 1) * Dd * 6144, 6144,
                     adj + (i + 1) * Dd,
                     &g_pre[j][0][0] - j * 1024, Dd,
                     &g_pre[i + 1][0][0], d0, j * 1024 + nloc, nch);
    } else {
        int u = g - (7 - j);
        int k = j + 1;
        mv_mma<false>(&sm, W_r + (size_t)k * Dd * Nn, Nn,
                      adj + k * Dd,
                      h, Nn,
                      &g_pre[j + 1][0][0], d0, (k + 1 + u) * 1024 + nloc, nch);
    }
}

// out = sig(g_pre[7]) @ W_o.T + b_o
__global__ void final_kernel(const float* __restrict__ W_o,
                             const float* __restrict__ b_o,
                             float* __restrict__ out)
{
    int idx = blockIdx.x * 256 + threadIdx.x;  // 2048
    int o = idx & 63, bt = idx >> 6;
    const float4* sr = (const float4*)&g_pre[7][bt][0];
    const float4* wr = (const float4*)(W_o + (size_t)o * Dd);
    float s = 0.f;
#pragma unroll 8
    for (int c = 0; c < 256; c++) {
        float4 aa = sr[c], bb = wr[c];
        s += sig(aa.x) * bb.x + sig(aa.y) * bb.y + sig(aa.z) * bb.z + sig(aa.w) * bb.w;
    }
    out[bt * 64 + o] = s + b_o[o];
}

// ---------------------------------------------------------------------------

extern "C" void kernel_launch(void* const* d_in, const int* in_sizes, int n_in,
                              void* d_out, int out_size)
{
    const float* x    = (const float*)d_in[0];
    const float* h    = (const float*)d_in[1];
    const int*   adj  = (const int*)d_in[2];
    const float* W_in = (const float*)d_in[3];
    const float* b_in = (const float*)d_in[4];
    const float* W_h  = (const float*)d_in[5];
    const float* b_h  = (const float*)d_in[6];
    const float* W_r  = (const float*)d_in[7];
    const float* W_s  = (const float*)d_in[8];
    const float* W_o  = (const float*)d_in[9];
    const float* b_o  = (const float*)d_in[10];
    float* out = (float*)d_out;

    init_kernel<<<1024, 256>>>(b_in, b_h);
    r0_kernel<<<dim3(8, 56), 256>>>(W_r, adj, h);
    prelayer_kernel<<<128, 256>>>(x, W_in);

    for (int j = 0; j < 7; j++) {
        int nch = (j <= 3) ? 4 : ((j <= 5) ? 2 : 1);
        int ksl = 1024 / (32 * nch);
        L_kernel<<<dim3(8, (13 - 2 * j) * ksl), 256>>>(
            W_h, W_s, W_r, adj, h, j, nch, ksl);
    }

    final_kernel<<<8, 256>>>(W_o, b_o, out);
}

// round 12
// speedup vs baseline: 1.6076x; 1.2185x over previous
#include <cuda_runtime.h>
#include <cstdint>

#define Nn 8192
#define Dd 1024

// Persistent scratch. g_pre[j] = PRE-activation of skips[j], j=0..7.
__device__ float g_pre[8][32][Dd];

#define APW 20   // uint32 words per bf16 tile row (16 data + 4 pad)

// Dynamic-smem workspace (59648 B): double-buffered raw W + ballot masks,
// single-buffered bf16 hi/lo planes.
struct SmemP {
    uint32_t Ah[128 * APW];        // masked W hi-plane (bf16x2)      10240 B
    uint32_t Al[128 * APW];        // lo-plane                        10240 B
    uint32_t Bh[32 * APW];         // activations hi                   2560 B
    uint32_t Bl[32 * APW];         // activations lo                   2560 B
    uint32_t kbit[2][32 * 5];      // ballot masks per buffer          1280 B
    float    Wraw[2][128 * 32];    // raw W tiles (cp.async dst)      32768 B
};
#define SMP_BYTES sizeof(SmemP)

__device__ __forceinline__ float sig(float v) {
    return 1.f / (1.f + __expf(-v));
}
__device__ __forceinline__ void redadd(float* p, float v) {
    asm volatile("red.global.add.f32 [%0], %1;" :: "l"(p), "f"(v) : "memory");
}
__device__ __forceinline__ uint32_t s2u(const void* p) {
    return (uint32_t)__cvta_generic_to_shared(p);
}
__device__ __forceinline__ void cpa16(uint32_t dst, const void* src) {
    asm volatile("cp.async.cg.shared.global [%0], [%1], 16;" :: "r"(dst), "l"(src));
}
__device__ __forceinline__ uint32_t pk2(float e1, float e0) {
    uint32_t r;
    asm("cvt.rn.bf16x2.f32 %0, %1, %2;" : "=r"(r) : "f"(e1), "f"(e0));
    return r;
}
__device__ __forceinline__ float lo_f(uint32_t r) { return __uint_as_float(r << 16); }
__device__ __forceinline__ float hi_f(uint32_t r) { return __uint_as_float(r & 0xFFFF0000u); }

__device__ __forceinline__ void split_store(uint32_t* Hp, uint32_t* Lp, float4 v) {
    uint32_t h01 = pk2(v.y, v.x);
    uint32_t h23 = pk2(v.w, v.z);
    float l0 = v.x - lo_f(h01), l1 = v.y - hi_f(h01);
    float l2 = v.z - lo_f(h23), l3 = v.w - hi_f(h23);
    *(uint2*)Hp = make_uint2(h01, h23);
    *(uint2*)Lp = make_uint2(pk2(l1, l0), pk2(l3, l2));
}

__device__ __forceinline__ void mma16(float* c,
                                      uint32_t a0, uint32_t a1, uint32_t a2, uint32_t a3,
                                      uint32_t b0, uint32_t b1) {
    asm volatile("mma.sync.aligned.m16n8k16.row.col.f32.bf16.bf16.f32 "
                 "{%0,%1,%2,%3}, {%4,%5,%6,%7}, {%8,%9}, {%0,%1,%2,%3};"
                 : "+f"(c[0]), "+f"(c[1]), "+f"(c[2]), "+f"(c[3])
                 : "r"(a0), "r"(a1), "r"(a2), "r"(a3), "r"(b0), "r"(b1));
}

// ---------------------------------------------------------------------------
// Masked matvec via mma.sync bf16 hi/lo split, chunk-pipelined:
//   out[b, d0+d] += sum_n act(X[b,n]) * W[d0+d,n] * (adjA[n*Nn + d0+d] != 0)
// Block 256 threads (8 warps), tile M=128 x N=32, K chunks of 32.
// W: cp.async double-buffer. adj: LDG one chunk ahead -> ballots after MMA.
// ---------------------------------------------------------------------------
template <bool SIG>
__device__ __forceinline__ void mv_mma(
    SmemP* sm,
    const float* __restrict__ W, int wstride,
    const int* __restrict__ adjA,
    const float* __restrict__ X, int xstride,
    float* __restrict__ out,
    int d0, int n0, int nchunks)
{
    const int tid  = threadIdx.x;
    const int wid  = tid >> 5, lane = tid & 31;
    const int g    = lane >> 2, tg = lane & 3;
    const int mw   = wid * 16;
    const int kq   = tid & 7;            // staging: 4-float k group
    const int dw   = tid >> 3;           // staging: 0..31
    const int jc   = dw & 3;             // ballot word select
    const int bsh  = dw >> 2;            // ballot bit base

    float c[4][4];
#pragma unroll
    for (int i = 0; i < 4; i++)
#pragma unroll
        for (int q = 0; q < 4; q++) c[i][q] = 0.f;

    int4   areg[4];
    float4 xcur, xnext;

    // ---- prologue: chunk 0 W cp.async + adj ballots + X ----
    {
        const int nb = n0;
#pragma unroll
        for (int p = 0; p < 4; p++) {
            int d = p * 32 + dw;
            cpa16(s2u(&sm->Wraw[0][d * 32 + kq * 4]),
                  &W[(size_t)(d0 + d) * wstride + nb + kq * 4]);
        }
        asm volatile("cp.async.commit_group;");
#pragma unroll
        for (int q = 0; q < 4; q++) {
            int k = q * 8 + wid;
            areg[q] = *(const int4*)&adjA[(size_t)(nb + k) * Nn + d0 + lane * 4];
        }
        xcur = *(const float4*)&X[(size_t)dw * xstride + nb + kq * 4];
#pragma unroll
        for (int q = 0; q < 4; q++) {
            int k = q * 8 + wid;
            uint32_t b0 = __ballot_sync(0xFFFFFFFFu, areg[q].x != 0);
            uint32_t b1 = __ballot_sync(0xFFFFFFFFu, areg[q].y != 0);
            uint32_t b2 = __ballot_sync(0xFFFFFFFFu, areg[q].z != 0);
            uint32_t b3 = __ballot_sync(0xFFFFFFFFu, areg[q].w != 0);
            if (lane < 4) {
                uint32_t v = (lane == 0) ? b0 : (lane == 1) ? b1
                           : (lane == 2) ? b2 : b3;
                sm->kbit[0][k * 5 + lane] = v;
            }
        }
    }

    for (int ch = 0; ch < nchunks; ch++) {
        const int buf = ch & 1;
        const bool more = (ch + 1 < nchunks);

        // ---- issue chunk c+1 loads (W cp.async, adj LDG, X LDG) ----
        if (more) {
            const int nb2 = n0 + (ch + 1) * 32;
#pragma unroll
            for (int p = 0; p < 4; p++) {
                int d = p * 32 + dw;
                cpa16(s2u(&sm->Wraw[buf ^ 1][d * 32 + kq * 4]),
                      &W[(size_t)(d0 + d) * wstride + nb2 + kq * 4]);
            }
            asm volatile("cp.async.commit_group;");
#pragma unroll
            for (int q = 0; q < 4; q++) {
                int k = q * 8 + wid;
                areg[q] = *(const int4*)&adjA[(size_t)(nb2 + k) * Nn + d0 + lane * 4];
            }
            xnext = *(const float4*)&X[(size_t)dw * xstride + nb2 + kq * 4];
            asm volatile("cp.async.wait_group 1;");
        } else {
            asm volatile("cp.async.wait_group 0;");
        }
        __syncthreads();   // W[ch] landed everywhere; prev MMA done; kbit[buf] ready

        // ---- staging: mask raw W via kbit, split to bf16 planes ----
        uint32_t m0 = sm->kbit[buf][(kq * 4 + 0) * 5 + jc];
        uint32_t m1 = sm->kbit[buf][(kq * 4 + 1) * 5 + jc];
        uint32_t m2 = sm->kbit[buf][(kq * 4 + 2) * 5 + jc];
        uint32_t m3 = sm->kbit[buf][(kq * 4 + 3) * 5 + jc];
#pragma unroll
        for (int p = 0; p < 4; p++) {
            int d = p * 32 + dw;
            int bp = p * 8 + bsh;        // = d >> 2
            float4 w = *(const float4*)&sm->Wraw[buf][d * 32 + kq * 4];
            if (!((m0 >> bp) & 1u)) w.x = 0.f;
            if (!((m1 >> bp) & 1u)) w.y = 0.f;
            if (!((m2 >> bp) & 1u)) w.z = 0.f;
            if (!((m3 >> bp) & 1u)) w.w = 0.f;
            split_store(&sm->Ah[d * APW + kq * 2], &sm->Al[d * APW + kq * 2], w);
        }
        {
            float4 xv = xcur;
            if (SIG) {
                xv.x = sig(xv.x); xv.y = sig(xv.y);
                xv.z = sig(xv.z); xv.w = sig(xv.w);
            }
            split_store(&sm->Bh[dw * APW + kq * 2], &sm->Bl[dw * APW + kq * 2], xv);
        }
        __syncthreads();

        // ---- MMA phase: 2 k16-steps x 4 n-tiles x (hh + hl + lh) ----
#pragma unroll
        for (int ks = 0; ks < 2; ks++) {
            int u  = ks * 8 + tg;
            int r0 = (mw + g) * APW, r1 = (mw + g + 8) * APW;
            uint32_t ah0 = sm->Ah[r0 + u],     ah1 = sm->Ah[r1 + u];
            uint32_t ah2 = sm->Ah[r0 + u + 4], ah3 = sm->Ah[r1 + u + 4];
            uint32_t al0 = sm->Al[r0 + u],     al1 = sm->Al[r1 + u];
            uint32_t al2 = sm->Al[r0 + u + 4], al3 = sm->Al[r1 + u + 4];
#pragma unroll
            for (int nt = 0; nt < 4; nt++) {
                int bb = (nt * 8 + g) * APW + u;
                uint32_t bh0 = sm->Bh[bb], bh1 = sm->Bh[bb + 4];
                uint32_t bl0 = sm->Bl[bb], bl1 = sm->Bl[bb + 4];
                mma16(c[nt], ah0, ah1, ah2, ah3, bh0, bh1);
                mma16(c[nt], ah0, ah1, ah2, ah3, bl0, bl1);
                mma16(c[nt], al0, al1, al2, al3, bh0, bh1);
            }
        }

        // ---- compress next chunk's adj to ballots; rotate X ----
        if (more) {
#pragma unroll
            for (int q = 0; q < 4; q++) {
                int k = q * 8 + wid;
                uint32_t b0 = __ballot_sync(0xFFFFFFFFu, areg[q].x != 0);
                uint32_t b1 = __ballot_sync(0xFFFFFFFFu, areg[q].y != 0);
                uint32_t b2 = __ballot_sync(0xFFFFFFFFu, areg[q].z != 0);
                uint32_t b3 = __ballot_sync(0xFFFFFFFFu, areg[q].w != 0);
                if (lane < 4) {
                    uint32_t v = (lane == 0) ? b0 : (lane == 1) ? b1
                               : (lane == 2) ? b2 : b3;
                    sm->kbit[buf ^ 1][k * 5 + lane] = v;
                }
            }
            xcur = xnext;
        }
    }

    // epilogue: C m16n8: c0:(g,2tg) c1:(g,2tg+1) c2:(g+8,2tg) c3:(g+8,2tg+1)
    const int drow = d0 + mw + g;
#pragma unroll
    for (int nt = 0; nt < 4; nt++) {
        int b = nt * 8 + 2 * tg;
        redadd(&out[(size_t)b       * Dd + drow],     c[nt][0]);
        redadd(&out[(size_t)(b + 1) * Dd + drow],     c[nt][1]);
        redadd(&out[(size_t)b       * Dd + drow + 8], c[nt][2]);
        redadd(&out[(size_t)(b + 1) * Dd + drow + 8], c[nt][3]);
    }
}

// ---------------------------------------------------------------------------

// g_pre[0][b][:] = b_in; g_pre[i][b][:] = b_h[i-1] for i=1..7  (float4)
__global__ void init_kernel(const float* __restrict__ b_in,
                            const float* __restrict__ b_h) {
    int idx = blockIdx.x * 256 + threadIdx.x;   // 256 blocks -> 65536 float4
    int fd = idx & 255;
    int i = idx >> 13;
    const float4* src = (i == 0) ? (const float4*)b_in
                                 : (const float4*)(b_h + (size_t)(i - 1) * Dd);
    ((float4*)g_pre)[idx] = src[fd];
}

// g_pre[0] += h @ Wr_m(0).T  (n in [1024, 8192)). grid (8, 56), nchunks=4.
__global__ void __launch_bounds__(256, 3) r0_kernel(
    const float* __restrict__ W_r, const int* __restrict__ adj,
    const float* __restrict__ h)
{
    extern __shared__ __align__(16) char dsm[];
    mv_mma<false>((SmemP*)dsm, W_r, Nn, adj, h, Nn, &g_pre[0][0][0],
                  blockIdx.x * 128, 1024 + blockIdx.y * 128, 4);
}

// g_pre[0] += x @ W_in.T
__global__ void prelayer_kernel(
    const float* __restrict__ x, const float* __restrict__ W_in)
{
    int idx = blockIdx.x * 256 + threadIdx.x;  // 32768
    int d = idx & 1023, bt = idx >> 10;
    const float4* xr = (const float4*)(x + bt * 256);
    const float4* wr = (const float4*)(W_in + (size_t)d * 256);
    float s = 0.f;
#pragma unroll 8
    for (int c = 0; c < 64; c++) {
        float4 aa = xr[c], bb = wr[c];
        s += aa.x * bb.x + aa.y * bb.y + aa.z * bb.z + aa.w * bb.w;
    }
    g_pre[0][bt][d] += s;
}

// Fused launch after g_pre[j] complete. grid (8, (13-2j)*ksl):
//   g == 0         : pre[j+1] += sig(pre[j]) @ Wh_m(j).T
//   g in [1, 7-j)  : pre[i+1] += sig(pre[j]) @ Ws-block(i, j).T  (i = j+g)
//   else           : pre[j+1] += h @ Wr_m(j+1).T slice
__global__ void __launch_bounds__(256, 3) L_kernel(
    const float* __restrict__ W_h, const float* __restrict__ W_s,
    const float* __restrict__ W_r, const int* __restrict__ adj,
    const float* __restrict__ h, int j, int nch, int ksl)
{
    extern __shared__ __align__(16) char dsm[];
    SmemP* sm = (SmemP*)dsm;
    int d0 = blockIdx.x * 128;
    int g = blockIdx.y / ksl;
    int nloc = (blockIdx.y % ksl) * 32 * nch;
    if (g == 0) {
        mv_mma<true>(sm, W_h + (size_t)j * Dd * Dd, Dd,
                     adj + (size_t)j * Dd * Nn + (j + 1) * Dd,
                     &g_pre[j][0][0], Dd,
                     &g_pre[j + 1][0][0], d0, nloc, nch);
    } else if (g <= 6 - j) {
        int i = j + g;
        // X rebased so X[b*Dd + n] == g_pre[j][b][n - j*1024]
        mv_mma<true>(sm, W_s + (size_t)(i - 1) * Dd * 6144, 6144,
                     adj + (i + 1) * Dd,
                     &g_pre[j][0][0] - j * 1024, Dd,
                     &g_pre[i + 1][0][0], d0, j * 1024 + nloc, nch);
    } else {
        int u = g - (7 - j);
        int k = j + 1;
        mv_mma<false>(sm, W_r + (size_t)k * Dd * Nn, Nn,
                      adj + k * Dd,
                      h, Nn,
                      &g_pre[j + 1][0][0], d0, (k + 1 + u) * 1024 + nloc, nch);
    }
}

// out = sig(g_pre[7]) @ W_o.T + b_o
__global__ void final_kernel(const float* __restrict__ W_o,
                             const float* __restrict__ b_o,
                             float* __restrict__ out)
{
    int idx = blockIdx.x * 256 + threadIdx.x;  // 2048
    int o = idx & 63, bt = idx >> 6;
    const float4* sr = (const float4*)&g_pre[7][bt][0];
    const float4* wr = (const float4*)(W_o + (size_t)o * Dd);
    float s = 0.f;
#pragma unroll 8
    for (int c = 0; c < 256; c++) {
        float4 aa = sr[c], bb = wr[c];
        s += sig(aa.x) * bb.x + sig(aa.y) * bb.y + sig(aa.z) * bb.z + sig(aa.w) * bb.w;
    }
    out[bt * 64 + o] = s + b_o[o];
}

// ---------------------------------------------------------------------------

extern "C" void kernel_launch(void* const* d_in, const int* in_sizes, int n_in,
                              void* d_out, int out_size)
{
    const float* x    = (const float*)d_in[0];
    const float* h    = (const float*)d_in[1];
    const int*   adj  = (const int*)d_in[2];
    const float* W_in = (const float*)d_in[3];
    const float* b_in = (const float*)d_in[4];
    const float* W_h  = (const float*)d_in[5];
    const float* b_h  = (const float*)d_in[6];
    const float* W_r  = (const float*)d_in[7];
    const float* W_s  = (const float*)d_in[8];
    const float* W_o  = (const float*)d_in[9];
    const float* b_o  = (const float*)d_in[10];
    float* out = (float*)d_out;

    static bool attr_done = false;
    if (!attr_done) {
        cudaFuncSetAttribute(r0_kernel,
            cudaFuncAttributeMaxDynamicSharedMemorySize, (int)SMP_BYTES);
        cudaFuncSetAttribute(L_kernel,
            cudaFuncAttributeMaxDynamicSharedMemorySize, (int)SMP_BYTES);
        attr_done = true;
    }

    init_kernel<<<256, 256>>>(b_in, b_h);
    r0_kernel<<<dim3(8, 56), 256, SMP_BYTES>>>(W_r, adj, h);
    prelayer_kernel<<<128, 256>>>(x, W_in);

    for (int j = 0; j < 7; j++) {
        int nch = (j <= 1) ? 8 : (j <= 3) ? 4 : (j <= 5) ? 2 : 1;
        int ksl = 1024 / (32 * nch);
        L_kernel<<<dim3(8, (13 - 2 * j) * ksl), 256, SMP_BYTES>>>(
            W_h, W_s, W_r, adj, h, j, nch, ksl);
    }

    final_kernel<<<8, 256>>>(W_o, b_o, out);
}

// round 13
// speedup vs baseline: 1.6226x; 1.0093x over previous
#include <cuda_runtime.h>
#include <cstdint>

#define Nn 8192
#define Dd 1024

// Persistent scratch. g_pre[j] = PRE-activation of skips[j], j=0..7.
__device__ float g_pre[8][32][Dd];

#define APW 20   // uint32 words per bf16 tile row (16 data + 4 pad)

// Dynamic-smem workspace (59648 B).
struct SmemP {
    uint32_t Ah[128 * APW];
    uint32_t Al[128 * APW];
    uint32_t Bh[32 * APW];
    uint32_t Bl[32 * APW];
    uint32_t kbit[2][32 * 5];
    float    Wraw[2][128 * 32];
};
#define SMP_BYTES sizeof(SmemP)

__device__ __forceinline__ float sig(float v) {
    return 1.f / (1.f + __expf(-v));
}
__device__ __forceinline__ void redadd(float* p, float v) {
    asm volatile("red.global.add.f32 [%0], %1;" :: "l"(p), "f"(v) : "memory");
}
__device__ __forceinline__ uint32_t s2u(const void* p) {
    return (uint32_t)__cvta_generic_to_shared(p);
}
__device__ __forceinline__ void cpa16(uint32_t dst, const void* src) {
    asm volatile("cp.async.cg.shared.global [%0], [%1], 16;" :: "r"(dst), "l"(src));
}
__device__ __forceinline__ uint32_t pk2(float e1, float e0) {
    uint32_t r;
    asm("cvt.rn.bf16x2.f32 %0, %1, %2;" : "=r"(r) : "f"(e1), "f"(e0));
    return r;
}
__device__ __forceinline__ float lo_f(uint32_t r) { return __uint_as_float(r << 16); }
__device__ __forceinline__ float hi_f(uint32_t r) { return __uint_as_float(r & 0xFFFF0000u); }

__device__ __forceinline__ void split_store(uint32_t* Hp, uint32_t* Lp, float4 v) {
    uint32_t h01 = pk2(v.y, v.x);
    uint32_t h23 = pk2(v.w, v.z);
    float l0 = v.x - lo_f(h01), l1 = v.y - hi_f(h01);
    float l2 = v.z - lo_f(h23), l3 = v.w - hi_f(h23);
    *(uint2*)Hp = make_uint2(h01, h23);
    *(uint2*)Lp = make_uint2(pk2(l1, l0), pk2(l3, l2));
}

__device__ __forceinline__ void mma16(float* c,
                                      uint32_t a0, uint32_t a1, uint32_t a2, uint32_t a3,
                                      uint32_t b0, uint32_t b1) {
    asm volatile("mma.sync.aligned.m16n8k16.row.col.f32.bf16.bf16.f32 "
                 "{%0,%1,%2,%3}, {%4,%5,%6,%7}, {%8,%9}, {%0,%1,%2,%3};"
                 : "+f"(c[0]), "+f"(c[1]), "+f"(c[2]), "+f"(c[3])
                 : "r"(a0), "r"(a1), "r"(a2), "r"(a3), "r"(b0), "r"(b1));
}

// ---------------------------------------------------------------------------
// Masked matvec via mma.sync bf16 hi/lo split, chunk-pipelined (R12, proven):
//   out[b, d0+d] += sum_n act(X[b,n]) * W[d0+d,n] * (adjA[n*Nn + d0+d] != 0)
// ---------------------------------------------------------------------------
template <bool SIG>
__device__ __forceinline__ void mv_mma(
    SmemP* sm,
    const float* __restrict__ W, int wstride,
    const int* __restrict__ adjA,
    const float* __restrict__ X, int xstride,
    float* __restrict__ out,
    int d0, int n0, int nchunks)
{
    const int tid  = threadIdx.x;
    const int wid  = tid >> 5, lane = tid & 31;
    const int g    = lane >> 2, tg = lane & 3;
    const int mw   = wid * 16;
    const int kq   = tid & 7;
    const int dw   = tid >> 3;
    const int jc   = dw & 3;
    const int bsh  = dw >> 2;

    float c[4][4];
#pragma unroll
    for (int i = 0; i < 4; i++)
#pragma unroll
        for (int q = 0; q < 4; q++) c[i][q] = 0.f;

    int4   areg[4];
    float4 xcur, xnext;

    {   // prologue: chunk 0
        const int nb = n0;
#pragma unroll
        for (int p = 0; p < 4; p++) {
            int d = p * 32 + dw;
            cpa16(s2u(&sm->Wraw[0][d * 32 + kq * 4]),
                  &W[(size_t)(d0 + d) * wstride + nb + kq * 4]);
        }
        asm volatile("cp.async.commit_group;");
#pragma unroll
        for (int q = 0; q < 4; q++) {
            int k = q * 8 + wid;
            areg[q] = *(const int4*)&adjA[(size_t)(nb + k) * Nn + d0 + lane * 4];
        }
        xcur = *(const float4*)&X[(size_t)dw * xstride + nb + kq * 4];
#pragma unroll
        for (int q = 0; q < 4; q++) {
            int k = q * 8 + wid;
            uint32_t b0 = __ballot_sync(0xFFFFFFFFu, areg[q].x != 0);
            uint32_t b1 = __ballot_sync(0xFFFFFFFFu, areg[q].y != 0);
            uint32_t b2 = __ballot_sync(0xFFFFFFFFu, areg[q].z != 0);
            uint32_t b3 = __ballot_sync(0xFFFFFFFFu, areg[q].w != 0);
            if (lane < 4) {
                uint32_t v = (lane == 0) ? b0 : (lane == 1) ? b1
                           : (lane == 2) ? b2 : b3;
                sm->kbit[0][k * 5 + lane] = v;
            }
        }
    }

    for (int ch = 0; ch < nchunks; ch++) {
        const int buf = ch & 1;
        const bool more = (ch + 1 < nchunks);

        if (more) {
            const int nb2 = n0 + (ch + 1) * 32;
#pragma unroll
            for (int p = 0; p < 4; p++) {
                int d = p * 32 + dw;
                cpa16(s2u(&sm->Wraw[buf ^ 1][d * 32 + kq * 4]),
                      &W[(size_t)(d0 + d) * wstride + nb2 + kq * 4]);
            }
            asm volatile("cp.async.commit_group;");
#pragma unroll
            for (int q = 0; q < 4; q++) {
                int k = q * 8 + wid;
                areg[q] = *(const int4*)&adjA[(size_t)(nb2 + k) * Nn + d0 + lane * 4];
            }
            xnext = *(const float4*)&X[(size_t)dw * xstride + nb2 + kq * 4];
            asm volatile("cp.async.wait_group 1;");
        } else {
            asm volatile("cp.async.wait_group 0;");
        }
        __syncthreads();

        uint32_t m0 = sm->kbit[buf][(kq * 4 + 0) * 5 + jc];
        uint32_t m1 = sm->kbit[buf][(kq * 4 + 1) * 5 + jc];
        uint32_t m2 = sm->kbit[buf][(kq * 4 + 2) * 5 + jc];
        uint32_t m3 = sm->kbit[buf][(kq * 4 + 3) * 5 + jc];
#pragma unroll
        for (int p = 0; p < 4; p++) {
            int d = p * 32 + dw;
            int bp = p * 8 + bsh;
            float4 w = *(const float4*)&sm->Wraw[buf][d * 32 + kq * 4];
            if (!((m0 >> bp) & 1u)) w.x = 0.f;
            if (!((m1 >> bp) & 1u)) w.y = 0.f;
            if (!((m2 >> bp) & 1u)) w.z = 0.f;
            if (!((m3 >> bp) & 1u)) w.w = 0.f;
            split_store(&sm->Ah[d * APW + kq * 2], &sm->Al[d * APW + kq * 2], w);
        }
        {
            float4 xv = xcur;
            if (SIG) {
                xv.x = sig(xv.x); xv.y = sig(xv.y);
                xv.z = sig(xv.z); xv.w = sig(xv.w);
            }
            split_store(&sm->Bh[dw * APW + kq * 2], &sm->Bl[dw * APW + kq * 2], xv);
        }
        __syncthreads();

#pragma unroll
        for (int ks = 0; ks < 2; ks++) {
            int u  = ks * 8 + tg;
            int r0 = (mw + g) * APW, r1 = (mw + g + 8) * APW;
            uint32_t ah0 = sm->Ah[r0 + u],     ah1 = sm->Ah[r1 + u];
            uint32_t ah2 = sm->Ah[r0 + u + 4], ah3 = sm->Ah[r1 + u + 4];
            uint32_t al0 = sm->Al[r0 + u],     al1 = sm->Al[r1 + u];
            uint32_t al2 = sm->Al[r0 + u + 4], al3 = sm->Al[r1 + u + 4];
#pragma unroll
            for (int nt = 0; nt < 4; nt++) {
                int bb = (nt * 8 + g) * APW + u;
                uint32_t bh0 = sm->Bh[bb], bh1 = sm->Bh[bb + 4];
                uint32_t bl0 = sm->Bl[bb], bl1 = sm->Bl[bb + 4];
                mma16(c[nt], ah0, ah1, ah2, ah3, bh0, bh1);
                mma16(c[nt], ah0, ah1, ah2, ah3, bl0, bl1);
                mma16(c[nt], al0, al1, al2, al3, bh0, bh1);
            }
        }

        if (more) {
#pragma unroll
            for (int q = 0; q < 4; q++) {
                int k = q * 8 + wid;
                uint32_t b0 = __ballot_sync(0xFFFFFFFFu, areg[q].x != 0);
                uint32_t b1 = __ballot_sync(0xFFFFFFFFu, areg[q].y != 0);
                uint32_t b2 = __ballot_sync(0xFFFFFFFFu, areg[q].z != 0);
                uint32_t b3 = __ballot_sync(0xFFFFFFFFu, areg[q].w != 0);
                if (lane < 4) {
                    uint32_t v = (lane == 0) ? b0 : (lane == 1) ? b1
                               : (lane == 2) ? b2 : b3;
                    sm->kbit[buf ^ 1][k * 5 + lane] = v;
                }
            }
            xcur = xnext;
        }
    }

    const int drow = d0 + mw + g;
#pragma unroll
    for (int nt = 0; nt < 4; nt++) {
        int b = nt * 8 + 2 * tg;
        redadd(&out[(size_t)b       * Dd + drow],     c[nt][0]);
        redadd(&out[(size_t)(b + 1) * Dd + drow],     c[nt][1]);
        redadd(&out[(size_t)b       * Dd + drow + 8], c[nt][2]);
        redadd(&out[(size_t)(b + 1) * Dd + drow + 8], c[nt][3]);
    }
}

// ---------------------------------------------------------------------------

// g_pre[0][b][:] = b_in; g_pre[i][b][:] = b_h[i-1] for i=1..7  (float4)
__global__ void init_kernel(const float* __restrict__ b_in,
                            const float* __restrict__ b_h) {
    int idx = blockIdx.x * 256 + threadIdx.x;   // 256 blocks -> 65536 float4
    int fd = idx & 255;
    int i = idx >> 13;
    const float4* src = (i == 0) ? (const float4*)b_in
                                 : (const float4*)(b_h + (size_t)(i - 1) * Dd);
    ((float4*)g_pre)[idx] = src[fd];
}

// pre[k] += h @ Wr_m(k).T  (n >= (k+1)*1024). grid (8, (7-k)*8), nch=4.
__global__ void __launch_bounds__(256, 3) Wr_kernel(
    const float* __restrict__ W_r, const int* __restrict__ adj,
    const float* __restrict__ h, int k)
{
    extern __shared__ __align__(16) char dsm[];
    mv_mma<false>((SmemP*)dsm, W_r + (size_t)k * Dd * Nn, Nn,
                  adj + k * Dd, h, Nn, &g_pre[k][0][0],
                  blockIdx.x * 128, (k + 1) * 1024 + blockIdx.y * 128, 4);
}

// g_pre[0] += x @ W_in.T   (ordered after Wr_0 via event)
__global__ void prelayer_kernel(
    const float* __restrict__ x, const float* __restrict__ W_in)
{
    int idx = blockIdx.x * 256 + threadIdx.x;  // 32768
    int d = idx & 1023, bt = idx >> 10;
    const float4* xr = (const float4*)(x + bt * 256);
    const float4* wr = (const float4*)(W_in + (size_t)d * 256);
    float s = 0.f;
#pragma unroll 8
    for (int c = 0; c < 64; c++) {
        float4 aa = xr[c], bb = wr[c];
        s += aa.x * bb.x + aa.y * bb.y + aa.z * bb.z + aa.w * bb.w;
    }
    g_pre[0][bt][d] += s;
}

// Serial-chain launch after pre[j] complete. grid (8, (7-j)*8), nch=4:
//   g == 0        : pre[j+1] += sig(pre[j]) @ Wh_m(j).T
//   g in [1, 7-j) : pre[i+1] += sig(pre[j]) @ Ws-block(i, j).T  (i = j+g)
__global__ void __launch_bounds__(256, 3) Lp_kernel(
    const float* __restrict__ W_h, const float* __restrict__ W_s,
    const int* __restrict__ adj, int j)
{
    extern __shared__ __align__(16) char dsm[];
    SmemP* sm = (SmemP*)dsm;
    int d0 = blockIdx.x * 128;
    int g = blockIdx.y >> 3;
    int nloc = (blockIdx.y & 7) * 128;
    if (g == 0) {
        mv_mma<true>(sm, W_h + (size_t)j * Dd * Dd, Dd,
                     adj + (size_t)j * Dd * Nn + (j + 1) * Dd,
                     &g_pre[j][0][0], Dd,
                     &g_pre[j + 1][0][0], d0, nloc, 4);
    } else {
        int i = j + g;
        // X rebased so X[b*Dd + n] == g_pre[j][b][n - j*1024]
        mv_mma<true>(sm, W_s + (size_t)(i - 1) * Dd * 6144, 6144,
                     adj + (i + 1) * Dd,
                     &g_pre[j][0][0] - j * 1024, Dd,
                     &g_pre[i + 1][0][0], d0, j * 1024 + nloc, 4);
    }
}

// out = sig(g_pre[7]) @ W_o.T + b_o
__global__ void final_kernel(const float* __restrict__ W_o,
                             const float* __restrict__ b_o,
                             float* __restrict__ out)
{
    int idx = blockIdx.x * 256 + threadIdx.x;  // 2048
    int o = idx & 63, bt = idx >> 6;
    const float4* sr = (const float4*)&g_pre[7][bt][0];
    const float4* wr = (const float4*)(W_o + (size_t)o * Dd);
    float s = 0.f;
#pragma unroll 8
    for (int c = 0; c < 256; c++) {
        float4 aa = sr[c], bb = wr[c];
        s += sig(aa.x) * bb.x + sig(aa.y) * bb.y + sig(aa.z) * bb.z + sig(aa.w) * bb.w;
    }
    out[bt * 64 + o] = s + b_o[o];
}

// ---------------------------------------------------------------------------

extern "C" void kernel_launch(void* const* d_in, const int* in_sizes, int n_in,
                              void* d_out, int out_size)
{
    const float* x    = (const float*)d_in[0];
    const float* h    = (const float*)d_in[1];
    const int*   adj  = (const int*)d_in[2];
    const float* W_in = (const float*)d_in[3];
    const float* b_in = (const float*)d_in[4];
    const float* W_h  = (const float*)d_in[5];
    const float* b_h  = (const float*)d_in[6];
    const float* W_r  = (const float*)d_in[7];
    const float* W_s  = (const float*)d_in[8];
    const float* W_o  = (const float*)d_in[9];
    const float* b_o  = (const float*)d_in[10];
    float* out = (float*)d_out;

    static cudaStream_t sB = nullptr;
    static cudaEvent_t eInit, eWr[7];
    if (!sB) {
        cudaStreamCreateWithFlags(&sB, cudaStreamNonBlocking);
        cudaEventCreateWithFlags(&eInit, cudaEventDisableTiming);
        for (int k = 0; k < 7; k++)
            cudaEventCreateWithFlags(&eWr[k], cudaEventDisableTiming);
        cudaFuncSetAttribute(Wr_kernel,
            cudaFuncAttributeMaxDynamicSharedMemorySize, (int)SMP_BYTES);
        cudaFuncSetAttribute(Lp_kernel,
            cudaFuncAttributeMaxDynamicSharedMemorySize, (int)SMP_BYTES);
    }

    // main stream: init; fork stream B for all h @ Wr work (independent chain)
    init_kernel<<<256, 256>>>(b_in, b_h);
    cudaEventRecord(eInit, 0);
    cudaStreamWaitEvent(sB, eInit, 0);
    for (int k = 0; k < 7; k++) {
        Wr_kernel<<<dim3(8, (7 - k) * 8), 256, SMP_BYTES, sB>>>(W_r, adj, h, k);
        cudaEventRecord(eWr[k], sB);
    }

    // serial chain on the main stream; joins B progressively via eWr[j]
    cudaStreamWaitEvent(0, eWr[0], 0);
    prelayer_kernel<<<128, 256>>>(x, W_in);

    for (int j = 0; j < 7; j++) {
        cudaStreamWaitEvent(0, eWr[j], 0);   // pre[j] complete (j=6 joins B fully)
        Lp_kernel<<<dim3(8, (7 - j) * 8), 256, SMP_BYTES>>>(W_h, W_s, adj, j);
    }

    final_kernel<<<8, 256>>>(W_o, b_o, out);
}